// round 7
// baseline (speedup 1.0000x reference)
#include <cuda_runtime.h>
#include <cstdint>

// ===========================================================================
// MHA B=2,S=2048,E=1024,H=16,D=64 fp32.  SIMT f32x2 everywhere.
//  - GEMMs: 128x128 tile, BK=8, duplicated-A smem (LDS.128 -> packed f32x2
//    operands, zero pack MOVs), __launch_bounds__(256,2) -> 2 CTAs/SM.
//  - flash attention: 2 Q rows/thread (BQ=256), halves broadcast LDS per
//    FFMA2, single wave (256 CTAs @ 2 CTAs/SM).
//  R7 fix: QSTR=68 (16B-aligned float4 rows; 65 caused misaligned LDS.128),
//  __align__(16) on static shared arrays read via ulonglong2.
// ===========================================================================

typedef unsigned long long ull;
#define DI __device__ __forceinline__

DI ull pk2(float lo, float hi) {
    ull r; asm("mov.b64 %0, {%1,%2};" : "=l"(r) : "f"(lo), "f"(hi)); return r;
}
DI void upk2(ull v, float& lo, float& hi) {
    asm("mov.b64 {%0,%1}, %2;" : "=f"(lo), "=f"(hi) : "l"(v));
}
DI ull ffma2(ull a, ull b, ull c) {
    ull d; asm("fma.rn.f32x2 %0, %1, %2, %3;" : "=l"(d) : "l"(a), "l"(b), "l"(c)); return d;
}
DI ull fmul2(ull a, ull b) {
    ull d; asm("mul.rn.f32x2 %0, %1, %2;" : "=l"(d) : "l"(a), "l"(b)); return d;
}

constexpr int B = 2, S = 2048, E = 1024, H = 16, D = 64;

__device__ float g_q[B * H * S * D];
__device__ float g_k[B * H * S * D];
__device__ float g_v[B * H * S * D];
__device__ float g_att[B * S * E];

// ---------------------------------------------------------------------------
// GEMM body: C[m,n] = sum_k X[m,k]*W[n,k] + bias[n]; 128x128 tile, BK=8.
// A stored DUPLICATED in smem: As2[kk][2r]=As2[kk][2r+1]=A[r] so that one
// LDS.128 yields two f32x2-dup operands. No pack MOVs in the inner loop.
// ---------------------------------------------------------------------------
template <int MODE>
DI void gemm_body(const float* __restrict__ X, const float* __restrict__ W,
                  const float* __restrict__ bias, float* __restrict__ out)
{
    __shared__ __align__(16) float As2[8][260];  // duplicated A (1040B rows, 16B mult)
    __shared__ __align__(16) float Ws[8][132];   // 528B rows, 16B mult

    const int tid = threadIdx.x;
    const int tx = tid & 15, ty = tid >> 4;
    const int m0 = blockIdx.y * 128;
    const int n0 = blockIdx.x * 128;
    const int lr = tid >> 1;        // 0..127
    const int lc = (tid & 1) << 2;  // 0 or 4

    const float* Xp = X + (size_t)(m0 + lr) * 1024 + lc;
    const float* Wp = W + (size_t)(n0 + lr) * 1024 + lc;

    ull acc[8][4];
#pragma unroll
    for (int i = 0; i < 8; i++)
#pragma unroll
        for (int j = 0; j < 4; j++) acc[i][j] = 0ull;

    float4 av = *(const float4*)Xp;
    float4 wv = *(const float4*)Wp;

    for (int k0 = 0; k0 < 1024; k0 += 8) {
        __syncthreads();
        {
            float2 d0 = {av.x, av.x}, d1 = {av.y, av.y};
            float2 d2 = {av.z, av.z}, d3 = {av.w, av.w};
            *(float2*)&As2[lc + 0][2 * lr] = d0;
            *(float2*)&As2[lc + 1][2 * lr] = d1;
            *(float2*)&As2[lc + 2][2 * lr] = d2;
            *(float2*)&As2[lc + 3][2 * lr] = d3;
            Ws[lc + 0][lr] = wv.x; Ws[lc + 1][lr] = wv.y;
            Ws[lc + 2][lr] = wv.z; Ws[lc + 3][lr] = wv.w;
        }
        __syncthreads();
        if (k0 + 8 < 1024) {
            av = *(const float4*)(Xp + k0 + 8);
            wv = *(const float4*)(Wp + k0 + 8);
        }
#pragma unroll
        for (int kk = 0; kk < 8; kk++) {
            // dup-A: each ulonglong2 = two f32x2-dup operands
            ulonglong2 au0 = *(const ulonglong2*)&As2[kk][8 * ty];
            ulonglong2 au1 = *(const ulonglong2*)&As2[kk][8 * ty + 4];
            ulonglong2 au2 = *(const ulonglong2*)&As2[kk][128 + 8 * ty];
            ulonglong2 au3 = *(const ulonglong2*)&As2[kk][128 + 8 * ty + 4];
            ulonglong2 b0 = *(const ulonglong2*)&Ws[kk][tx * 4];
            ulonglong2 b1 = *(const ulonglong2*)&Ws[kk][64 + tx * 4];
            ull a2[8] = {au0.x, au0.y, au1.x, au1.y, au2.x, au2.y, au3.x, au3.y};
            ull bv[4] = {b0.x, b0.y, b1.x, b1.y};
#pragma unroll
            for (int i = 0; i < 8; i++)
#pragma unroll
                for (int j = 0; j < 4; j++) acc[i][j] = ffma2(a2[i], bv[j], acc[i][j]);
        }
    }

    float4 bias0 = *(const float4*)&bias[n0 + tx * 4];
    float4 bias1 = *(const float4*)&bias[n0 + 64 + tx * 4];

#pragma unroll
    for (int i = 0; i < 8; i++) {
        int m = m0 + (i >> 2) * 64 + ty * 4 + (i & 3);
        float4 r0, r1;
        upk2(acc[i][0], r0.x, r0.y); upk2(acc[i][1], r0.z, r0.w);
        upk2(acc[i][2], r1.x, r1.y); upk2(acc[i][3], r1.z, r1.w);
        r0.x += bias0.x; r0.y += bias0.y; r0.z += bias0.z; r0.w += bias0.w;
        r1.x += bias1.x; r1.y += bias1.y; r1.z += bias1.z; r1.w += bias1.w;
        if (MODE == 0) {
            int bb = m >> 11, ss = m & 2047;
            int nA = n0 + tx * 4;
            int nB = n0 + 64 + tx * 4;
            int hA = nA >> 6, dA = nA & 63;
            int hB = nB >> 6, dB = nB & 63;
            *(float4*)&out[((size_t)(bb * H + hA) * S + ss) * D + dA] = r0;
            *(float4*)&out[((size_t)(bb * H + hB) * S + ss) * D + dB] = r1;
        } else {
            *(float4*)&out[(size_t)m * 1024 + n0 + tx * 4] = r0;
            *(float4*)&out[(size_t)m * 1024 + n0 + 64 + tx * 4] = r1;
        }
    }
}

__global__ __launch_bounds__(256, 2) void gemm_proj(const float* __restrict__ xq,
                                                    const float* __restrict__ xk,
                                                    const float* __restrict__ xv,
                                                    const float* __restrict__ Wq,
                                                    const float* __restrict__ Wk,
                                                    const float* __restrict__ Wv,
                                                    const float* __restrict__ bq,
                                                    const float* __restrict__ bk,
                                                    const float* __restrict__ bv,
                                                    float* __restrict__ oq,
                                                    float* __restrict__ ok,
                                                    float* __restrict__ ov)
{
    const int z = blockIdx.z;
    const float* X = (z == 0) ? xq : (z == 1) ? xk : xv;
    const float* W = (z == 0) ? Wq : (z == 1) ? Wk : Wv;
    const float* bb = (z == 0) ? bq : (z == 1) ? bk : bv;
    float* out = (z == 0) ? oq : (z == 1) ? ok : ov;
    gemm_body<0>(X, W, bb, out);
}

__global__ __launch_bounds__(256, 2) void gemm_out(const float* __restrict__ X,
                                                   const float* __restrict__ W,
                                                   const float* __restrict__ bias,
                                                   float* __restrict__ out)
{
    gemm_body<1>(X, W, bias, out);
}

// ---------------------------------------------------------------------------
// flash attention: BQ=256 rows/CTA, 128 threads, 2 rows/thread.
// Q smem stride 68 (16B-aligned float4 rows, conflict-free LDS.128).
// K tile transposed [d][68]; V row-major [j][64]. Group-wise online softmax.
// ---------------------------------------------------------------------------
constexpr int BQ = 256, TK = 64;
constexpr int QSTR = 68, KSTR = 68;
constexpr int ATTN_SMEM = (BQ * QSTR + D * KSTR + TK * D) * 4;  // 103424

__global__ __launch_bounds__(128) void attn_kernel(const float* __restrict__ Q,
                                                   const float* __restrict__ K,
                                                   const float* __restrict__ V,
                                                   float* __restrict__ Oout)
{
    extern __shared__ float sm[];
    float* Qs  = sm;                  // [256][68]
    float* Kst = sm + BQ * QSTR;      // [64 d][68 keys]
    float* Vs  = Kst + D * KSTR;      // [64 keys][64 d]

    const int t  = threadIdx.x;
    const int bh = blockIdx.y;
    const int q0 = blockIdx.x * BQ;
    const float* Qb = Q + (size_t)bh * (S * D);
    const float* Kb = K + (size_t)bh * (S * D);
    const float* Vb = V + (size_t)bh * (S * D);

    const int dl = t & 63, rb = t >> 6;

#pragma unroll 8
    for (int i = 0; i < 128; i++) {
        int r = 2 * i + rb;
        Qs[r * QSTR + dl] = Qb[(size_t)(q0 + r) * D + dl] * 0.125f;
    }

    ull oa[32], ob[32];
#pragma unroll
    for (int i = 0; i < 32; i++) { oa[i] = 0ull; ob[i] = 0ull; }
    float ma = -3.0e38f, la = 0.0f, mb = -3.0e38f, lb = 0.0f;

    const int r0 = t, r1 = t + 128;

    for (int kt = 0; kt < S; kt += TK) {
        __syncthreads();
#pragma unroll
        for (int i = 0; i < 32; i++) {
            int j = 2 * i + rb;
            Kst[dl * KSTR + j] = Kb[(size_t)(kt + j) * D + dl];
            Vs[j * D + dl]     = Vb[(size_t)(kt + j) * D + dl];
        }
        __syncthreads();

#pragma unroll
        for (int g = 0; g < 4; g++) {
            ull sa[8], sb2[8];
#pragma unroll
            for (int i = 0; i < 8; i++) { sa[i] = 0ull; sb2[i] = 0ull; }

#pragma unroll
            for (int dc = 0; dc < D; dc += 16) {
                float qa[16], qb[16];
#pragma unroll
                for (int u = 0; u < 4; u++) {
                    *(float4*)&qa[4 * u] = *(const float4*)&Qs[r0 * QSTR + dc + 4 * u];
                    *(float4*)&qb[4 * u] = *(const float4*)&Qs[r1 * QSTR + dc + 4 * u];
                }
#pragma unroll
                for (int dd = 0; dd < 16; dd++) {
                    ull q2a = pk2(qa[dd], qa[dd]);
                    ull q2b = pk2(qb[dd], qb[dd]);
                    const ulonglong2* kr = (const ulonglong2*)&Kst[(dc + dd) * KSTR];
#pragma unroll
                    for (int u = 0; u < 4; u++) {
                        ulonglong2 kv = kr[g * 4 + u];
                        sa[2 * u]      = ffma2(q2a, kv.x, sa[2 * u]);
                        sa[2 * u + 1]  = ffma2(q2a, kv.y, sa[2 * u + 1]);
                        sb2[2 * u]     = ffma2(q2b, kv.x, sb2[2 * u]);
                        sb2[2 * u + 1] = ffma2(q2b, kv.y, sb2[2 * u + 1]);
                    }
                }
            }

            // online softmax, row a
            {
                float gmax = -3.0e38f;
#pragma unroll
                for (int i = 0; i < 8; i++) {
                    float x, y; upk2(sa[i], x, y);
                    gmax = fmaxf(gmax, fmaxf(x, y));
                }
                if (__any_sync(0xffffffffu, gmax > ma)) {
                    float mnew = fmaxf(ma, gmax);
                    float alpha = __expf(ma - mnew);
                    la *= alpha;
                    ull al2 = pk2(alpha, alpha);
#pragma unroll
                    for (int i = 0; i < 32; i++) oa[i] = fmul2(oa[i], al2);
                    ma = mnew;
                }
                float lsum = 0.0f;
#pragma unroll
                for (int i = 0; i < 8; i++) {
                    float x, y; upk2(sa[i], x, y);
                    float p0 = __expf(x - ma), p1 = __expf(y - ma);
                    lsum += p0 + p1;
                    sa[i] = pk2(p0, p1);
                }
                la += lsum;
            }
            // online softmax, row b
            {
                float gmax = -3.0e38f;
#pragma unroll
                for (int i = 0; i < 8; i++) {
                    float x, y; upk2(sb2[i], x, y);
                    gmax = fmaxf(gmax, fmaxf(x, y));
                }
                if (__any_sync(0xffffffffu, gmax > mb)) {
                    float mnew = fmaxf(mb, gmax);
                    float alpha = __expf(mb - mnew);
                    lb *= alpha;
                    ull al2 = pk2(alpha, alpha);
#pragma unroll
                    for (int i = 0; i < 32; i++) ob[i] = fmul2(ob[i], al2);
                    mb = mnew;
                }
                float lsum = 0.0f;
#pragma unroll
                for (int i = 0; i < 8; i++) {
                    float x, y; upk2(sb2[i], x, y);
                    float p0 = __expf(x - mb), p1 = __expf(y - mb);
                    lsum += p0 + p1;
                    sb2[i] = pk2(p0, p1);
                }
                lb += lsum;
            }

            // PV: V loads shared by both rows
#pragma unroll
            for (int j2 = 0; j2 < 8; j2++) {
                int j = g * 16 + 2 * j2;
                float pa0, pa1, pb0, pb1;
                upk2(sa[j2], pa0, pa1);
                upk2(sb2[j2], pb0, pb1);
                ull paa = pk2(pa0, pa0), pab = pk2(pa1, pa1);
                ull pba = pk2(pb0, pb0), pbb = pk2(pb1, pb1);
                const ulonglong2* v0 = (const ulonglong2*)&Vs[j * D];
                const ulonglong2* v1 = (const ulonglong2*)&Vs[(j + 1) * D];
#pragma unroll
                for (int cp = 0; cp < 16; cp++) {
                    ulonglong2 va = v0[cp];
                    ulonglong2 vb = v1[cp];
                    oa[2 * cp]     = ffma2(paa, va.x, oa[2 * cp]);
                    oa[2 * cp + 1] = ffma2(paa, va.y, oa[2 * cp + 1]);
                    oa[2 * cp]     = ffma2(pab, vb.x, oa[2 * cp]);
                    oa[2 * cp + 1] = ffma2(pab, vb.y, oa[2 * cp + 1]);
                    ob[2 * cp]     = ffma2(pba, va.x, ob[2 * cp]);
                    ob[2 * cp + 1] = ffma2(pba, va.y, ob[2 * cp + 1]);
                    ob[2 * cp]     = ffma2(pbb, vb.x, ob[2 * cp]);
                    ob[2 * cp + 1] = ffma2(pbb, vb.y, ob[2 * cp + 1]);
                }
            }
        }
    }

    const int bb = bh >> 4, hh = bh & 15;
    {
        float inv_l = 1.0f / la;
        float* dst = Oout + (size_t)(bb * S + q0 + r0) * E + hh * D;
#pragma unroll
        for (int cp = 0; cp < 16; cp++) {
            float x0, x1, x2, x3;
            upk2(oa[2 * cp], x0, x1);
            upk2(oa[2 * cp + 1], x2, x3);
            float4 o4 = { x0 * inv_l, x1 * inv_l, x2 * inv_l, x3 * inv_l };
            *(float4*)&dst[cp * 4] = o4;
        }
    }
    {
        float inv_l = 1.0f / lb;
        float* dst = Oout + (size_t)(bb * S + q0 + r1) * E + hh * D;
#pragma unroll
        for (int cp = 0; cp < 16; cp++) {
            float x0, x1, x2, x3;
            upk2(ob[2 * cp], x0, x1);
            upk2(ob[2 * cp + 1], x2, x3);
            float4 o4 = { x0 * inv_l, x1 * inv_l, x2 * inv_l, x3 * inv_l };
            *(float4*)&dst[cp * 4] = o4;
        }
    }
}

// ---------------------------------------------------------------------------
extern "C" void kernel_launch(void* const* d_in, const int* in_sizes, int n_in,
                              void* d_out, int out_size)
{
    const float* query = (const float*)d_in[0];
    const float* key   = (const float*)d_in[1];
    const float* value = (const float*)d_in[2];
    const float* Wq    = (const float*)d_in[3];
    const float* bq    = (const float*)d_in[4];
    const float* Wk    = (const float*)d_in[5];
    const float* bk    = (const float*)d_in[6];
    const float* Wv    = (const float*)d_in[7];
    const float* bv    = (const float*)d_in[8];
    const float* Wo    = (const float*)d_in[9];
    const float* bo    = (const float*)d_in[10];

    void *pq, *pk, *pv, *patt;
    cudaGetSymbolAddress(&pq, g_q);
    cudaGetSymbolAddress(&pk, g_k);
    cudaGetSymbolAddress(&pv, g_v);
    cudaGetSymbolAddress(&patt, g_att);

    cudaFuncSetAttribute(attn_kernel, cudaFuncAttributeMaxDynamicSharedMemorySize,
                         ATTN_SMEM);

    dim3 pgrid(8, 32, 3);
    gemm_proj<<<pgrid, 256>>>(query, key, value, Wq, Wk, Wv, bq, bk, bv,
                              (float*)pq, (float*)pk, (float*)pv);

    dim3 agrid(S / BQ, B * H);  // (8, 32)
    attn_kernel<<<agrid, 128, ATTN_SMEM>>>((const float*)pq, (const float*)pk,
                                           (const float*)pv, (float*)patt);

    dim3 ggrid(8, 32);
    gemm_out<<<ggrid, 256>>>((const float*)patt, Wo, bo, (float*)d_out);
}

// round 8
// speedup vs baseline: 1.0426x; 1.0426x over previous
#include <cuda_runtime.h>
#include <cstdint>

// ===========================================================================
// MHA B=2,S=2048,E=1024,H=16,D=64 fp32.  SIMT f32x2 everywhere.
//  - GEMMs: exact R5 engine (128x128, BK=8, pk2-dup in regs) — measured best.
//  - attention: 2 Q rows/thread (BQ=256), register-tight (d-block 8, one kv
//    live at a time) to stay under 255 regs; K/V LDS shared by both rows.
// ===========================================================================

typedef unsigned long long ull;
#define DI __device__ __forceinline__

DI ull pk2(float lo, float hi) {
    ull r; asm("mov.b64 %0, {%1,%2};" : "=l"(r) : "f"(lo), "f"(hi)); return r;
}
DI void upk2(ull v, float& lo, float& hi) {
    asm("mov.b64 {%0,%1}, %2;" : "=f"(lo), "=f"(hi) : "l"(v));
}
DI ull ffma2(ull a, ull b, ull c) {
    ull d; asm("fma.rn.f32x2 %0, %1, %2, %3;" : "=l"(d) : "l"(a), "l"(b), "l"(c)); return d;
}
DI ull fmul2(ull a, ull b) {
    ull d; asm("mul.rn.f32x2 %0, %1, %2;" : "=l"(d) : "l"(a), "l"(b)); return d;
}

constexpr int B = 2, S = 2048, E = 1024, H = 16, D = 64;

__device__ float g_q[B * H * S * D];
__device__ float g_k[B * H * S * D];
__device__ float g_v[B * H * S * D];
__device__ float g_att[B * S * E];

// ---------------------------------------------------------------------------
// R5 GEMM engine (measured 576us proj / ~192us out). Unchanged.
// ---------------------------------------------------------------------------
template <int MODE>
DI void gemm_body(const float* __restrict__ X, const float* __restrict__ W,
                  const float* __restrict__ bias, float* __restrict__ out)
{
    __shared__ __align__(16) float As[8][132];
    __shared__ __align__(16) float Ws[8][132];

    const int tid = threadIdx.x;
    const int tx = tid & 15, ty = tid >> 4;
    const int m0 = blockIdx.y * 128;
    const int n0 = blockIdx.x * 128;
    const int lr = tid >> 1;
    const int lc = (tid & 1) << 2;

    const float* Xp = X + (size_t)(m0 + lr) * 1024 + lc;
    const float* Wp = W + (size_t)(n0 + lr) * 1024 + lc;

    ull acc[8][4];
#pragma unroll
    for (int i = 0; i < 8; i++)
#pragma unroll
        for (int j = 0; j < 4; j++) acc[i][j] = 0ull;

    float4 av = *(const float4*)Xp;
    float4 wv = *(const float4*)Wp;

    for (int k0 = 0; k0 < 1024; k0 += 8) {
        __syncthreads();
        As[lc + 0][lr] = av.x; As[lc + 1][lr] = av.y;
        As[lc + 2][lr] = av.z; As[lc + 3][lr] = av.w;
        Ws[lc + 0][lr] = wv.x; Ws[lc + 1][lr] = wv.y;
        Ws[lc + 2][lr] = wv.z; Ws[lc + 3][lr] = wv.w;
        __syncthreads();
        if (k0 + 8 < 1024) {
            av = *(const float4*)(Xp + k0 + 8);
            wv = *(const float4*)(Wp + k0 + 8);
        }
#pragma unroll
        for (int kk = 0; kk < 8; kk++) {
            float4 a0 = *(const float4*)&As[kk][ty * 4];
            float4 a1 = *(const float4*)&As[kk][64 + ty * 4];
            ulonglong2 b0 = *(const ulonglong2*)&Ws[kk][tx * 4];
            ulonglong2 b1 = *(const ulonglong2*)&Ws[kk][64 + tx * 4];
            float a[8] = {a0.x, a0.y, a0.z, a0.w, a1.x, a1.y, a1.z, a1.w};
            ull bv[4] = {b0.x, b0.y, b1.x, b1.y};
#pragma unroll
            for (int i = 0; i < 8; i++) {
                ull a2 = pk2(a[i], a[i]);
#pragma unroll
                for (int j = 0; j < 4; j++) acc[i][j] = ffma2(a2, bv[j], acc[i][j]);
            }
        }
    }

    float4 bias0 = *(const float4*)&bias[n0 + tx * 4];
    float4 bias1 = *(const float4*)&bias[n0 + 64 + tx * 4];

#pragma unroll
    for (int i = 0; i < 8; i++) {
        int m = m0 + (i >> 2) * 64 + ty * 4 + (i & 3);
        float4 r0, r1;
        upk2(acc[i][0], r0.x, r0.y); upk2(acc[i][1], r0.z, r0.w);
        upk2(acc[i][2], r1.x, r1.y); upk2(acc[i][3], r1.z, r1.w);
        r0.x += bias0.x; r0.y += bias0.y; r0.z += bias0.z; r0.w += bias0.w;
        r1.x += bias1.x; r1.y += bias1.y; r1.z += bias1.z; r1.w += bias1.w;
        if (MODE == 0) {
            int bb = m >> 11, ss = m & 2047;
            int nA = n0 + tx * 4;
            int nB = n0 + 64 + tx * 4;
            int hA = nA >> 6, dA = nA & 63;
            int hB = nB >> 6, dB = nB & 63;
            *(float4*)&out[((size_t)(bb * H + hA) * S + ss) * D + dA] = r0;
            *(float4*)&out[((size_t)(bb * H + hB) * S + ss) * D + dB] = r1;
        } else {
            *(float4*)&out[(size_t)m * 1024 + n0 + tx * 4] = r0;
            *(float4*)&out[(size_t)m * 1024 + n0 + 64 + tx * 4] = r1;
        }
    }
}

__global__ __launch_bounds__(256) void gemm_proj(const float* __restrict__ xq,
                                                 const float* __restrict__ xk,
                                                 const float* __restrict__ xv,
                                                 const float* __restrict__ Wq,
                                                 const float* __restrict__ Wk,
                                                 const float* __restrict__ Wv,
                                                 const float* __restrict__ bq,
                                                 const float* __restrict__ bk,
                                                 const float* __restrict__ bv,
                                                 float* __restrict__ oq,
                                                 float* __restrict__ ok,
                                                 float* __restrict__ ov)
{
    const int z = blockIdx.z;
    const float* X = (z == 0) ? xq : (z == 1) ? xk : xv;
    const float* W = (z == 0) ? Wq : (z == 1) ? Wk : Wv;
    const float* bb = (z == 0) ? bq : (z == 1) ? bk : bv;
    float* out = (z == 0) ? oq : (z == 1) ? ok : ov;
    gemm_body<0>(X, W, bb, out);
}

__global__ __launch_bounds__(256) void gemm_out(const float* __restrict__ X,
                                                const float* __restrict__ W,
                                                const float* __restrict__ bias,
                                                float* __restrict__ out)
{
    gemm_body<1>(X, W, bias, out);
}

// ---------------------------------------------------------------------------
// flash attention: BQ=256, 128 threads, 2 rows/thread. Register-tight:
// d-block of 8 (qa/qb 8 floats each), one kv ulonglong2 live at a time.
// Q stride 68 (16B-aligned rows). Group-wise online softmax, 16 keys/group.
// ---------------------------------------------------------------------------
constexpr int BQ = 256, TK = 64;
constexpr int QSTR = 68, KSTR = 68;
constexpr int ATTN_SMEM = (BQ * QSTR + D * KSTR + TK * D) * 4;  // 103424

__global__ __launch_bounds__(128) void attn_kernel(const float* __restrict__ Q,
                                                   const float* __restrict__ K,
                                                   const float* __restrict__ V,
                                                   float* __restrict__ Oout)
{
    extern __shared__ float sm[];
    float* Qs  = sm;                  // [256][68]
    float* Kst = sm + BQ * QSTR;      // [64 d][68 keys]
    float* Vs  = Kst + D * KSTR;      // [64 keys][64 d]

    const int t  = threadIdx.x;
    const int bh = blockIdx.y;
    const int q0 = blockIdx.x * BQ;
    const float* Qb = Q + (size_t)bh * (S * D);
    const float* Kb = K + (size_t)bh * (S * D);
    const float* Vb = V + (size_t)bh * (S * D);

    const int dl = t & 63, rb = t >> 6;

#pragma unroll 8
    for (int i = 0; i < 128; i++) {
        int r = 2 * i + rb;
        Qs[r * QSTR + dl] = Qb[(size_t)(q0 + r) * D + dl] * 0.125f;
    }

    ull oa[32], ob[32];
#pragma unroll
    for (int i = 0; i < 32; i++) { oa[i] = 0ull; ob[i] = 0ull; }
    float ma = -3.0e38f, la = 0.0f, mb = -3.0e38f, lb = 0.0f;

    const float* qrow0 = &Qs[t * QSTR];
    const float* qrow1 = &Qs[(t + 128) * QSTR];

    for (int kt = 0; kt < S; kt += TK) {
        __syncthreads();
#pragma unroll
        for (int i = 0; i < 32; i++) {
            int j = 2 * i + rb;
            Kst[dl * KSTR + j] = Kb[(size_t)(kt + j) * D + dl];
            Vs[j * D + dl]     = Vb[(size_t)(kt + j) * D + dl];
        }
        __syncthreads();

#pragma unroll
        for (int g = 0; g < 4; g++) {
            ull sa[8], sb2[8];
#pragma unroll
            for (int i = 0; i < 8; i++) { sa[i] = 0ull; sb2[i] = 0ull; }

            // scores: d in blocks of 8 (keeps q live-set at 16 floats)
#pragma unroll
            for (int dc = 0; dc < D; dc += 8) {
                float qa[8], qb[8];
                *(float4*)&qa[0] = *(const float4*)&qrow0[dc];
                *(float4*)&qa[4] = *(const float4*)&qrow0[dc + 4];
                *(float4*)&qb[0] = *(const float4*)&qrow1[dc];
                *(float4*)&qb[4] = *(const float4*)&qrow1[dc + 4];
#pragma unroll
                for (int dd = 0; dd < 8; dd++) {
                    ull q2a = pk2(qa[dd], qa[dd]);
                    ull q2b = pk2(qb[dd], qb[dd]);
                    const ulonglong2* kr =
                        (const ulonglong2*)&Kst[(dc + dd) * KSTR + g * 16];
#pragma unroll
                    for (int u = 0; u < 4; u++) {
                        ulonglong2 kv = kr[u];
                        sa[2 * u]      = ffma2(q2a, kv.x, sa[2 * u]);
                        sa[2 * u + 1]  = ffma2(q2a, kv.y, sa[2 * u + 1]);
                        sb2[2 * u]     = ffma2(q2b, kv.x, sb2[2 * u]);
                        sb2[2 * u + 1] = ffma2(q2b, kv.y, sb2[2 * u + 1]);
                    }
                }
            }

            // online softmax, row a
            {
                float gmax = -3.0e38f;
#pragma unroll
                for (int i = 0; i < 8; i++) {
                    float x, y; upk2(sa[i], x, y);
                    gmax = fmaxf(gmax, fmaxf(x, y));
                }
                if (__any_sync(0xffffffffu, gmax > ma)) {
                    float mnew = fmaxf(ma, gmax);
                    float alpha = __expf(ma - mnew);
                    la *= alpha;
                    ull al2 = pk2(alpha, alpha);
#pragma unroll
                    for (int i = 0; i < 32; i++) oa[i] = fmul2(oa[i], al2);
                    ma = mnew;
                }
                float lsum = 0.0f;
#pragma unroll
                for (int i = 0; i < 8; i++) {
                    float x, y; upk2(sa[i], x, y);
                    float p0 = __expf(x - ma), p1 = __expf(y - ma);
                    lsum += p0 + p1;
                    sa[i] = pk2(p0, p1);
                }
                la += lsum;
            }
            // online softmax, row b
            {
                float gmax = -3.0e38f;
#pragma unroll
                for (int i = 0; i < 8; i++) {
                    float x, y; upk2(sb2[i], x, y);
                    gmax = fmaxf(gmax, fmaxf(x, y));
                }
                if (__any_sync(0xffffffffu, gmax > mb)) {
                    float mnew = fmaxf(mb, gmax);
                    float alpha = __expf(mb - mnew);
                    lb *= alpha;
                    ull al2 = pk2(alpha, alpha);
#pragma unroll
                    for (int i = 0; i < 32; i++) ob[i] = fmul2(ob[i], al2);
                    mb = mnew;
                }
                float lsum = 0.0f;
#pragma unroll
                for (int i = 0; i < 8; i++) {
                    float x, y; upk2(sb2[i], x, y);
                    float p0 = __expf(x - mb), p1 = __expf(y - mb);
                    lsum += p0 + p1;
                    sb2[i] = pk2(p0, p1);
                }
                lb += lsum;
            }

            // PV: V loads shared by both rows
#pragma unroll
            for (int j2 = 0; j2 < 8; j2++) {
                int j = g * 16 + 2 * j2;
                float pa0, pa1, pb0, pb1;
                upk2(sa[j2], pa0, pa1);
                upk2(sb2[j2], pb0, pb1);
                ull paa = pk2(pa0, pa0), pab = pk2(pa1, pa1);
                ull pba = pk2(pb0, pb0), pbb = pk2(pb1, pb1);
                const ulonglong2* v0 = (const ulonglong2*)&Vs[j * D];
                const ulonglong2* v1 = (const ulonglong2*)&Vs[(j + 1) * D];
#pragma unroll
                for (int cp = 0; cp < 16; cp++) {
                    ulonglong2 va = v0[cp];
                    oa[2 * cp]     = ffma2(paa, va.x, oa[2 * cp]);
                    oa[2 * cp + 1] = ffma2(paa, va.y, oa[2 * cp + 1]);
                    ob[2 * cp]     = ffma2(pba, va.x, ob[2 * cp]);
                    ob[2 * cp + 1] = ffma2(pba, va.y, ob[2 * cp + 1]);
                    ulonglong2 vb = v1[cp];
                    oa[2 * cp]     = ffma2(pab, vb.x, oa[2 * cp]);
                    oa[2 * cp + 1] = ffma2(pab, vb.y, oa[2 * cp + 1]);
                    ob[2 * cp]     = ffma2(pbb, vb.x, ob[2 * cp]);
                    ob[2 * cp + 1] = ffma2(pbb, vb.y, ob[2 * cp + 1]);
                }
            }
        }
    }

    const int bb = bh >> 4, hh = bh & 15;
    {
        float inv_l = 1.0f / la;
        float* dst = Oout + (size_t)(bb * S + q0 + t) * E + hh * D;
#pragma unroll
        for (int cp = 0; cp < 16; cp++) {
            float x0, x1, x2, x3;
            upk2(oa[2 * cp], x0, x1);
            upk2(oa[2 * cp + 1], x2, x3);
            float4 o4 = { x0 * inv_l, x1 * inv_l, x2 * inv_l, x3 * inv_l };
            *(float4*)&dst[cp * 4] = o4;
        }
    }
    {
        float inv_l = 1.0f / lb;
        float* dst = Oout + (size_t)(bb * S + q0 + t + 128) * E + hh * D;
#pragma unroll
        for (int cp = 0; cp < 16; cp++) {
            float x0, x1, x2, x3;
            upk2(ob[2 * cp], x0, x1);
            upk2(ob[2 * cp + 1], x2, x3);
            float4 o4 = { x0 * inv_l, x1 * inv_l, x2 * inv_l, x3 * inv_l };
            *(float4*)&dst[cp * 4] = o4;
        }
    }
}

// ---------------------------------------------------------------------------
extern "C" void kernel_launch(void* const* d_in, const int* in_sizes, int n_in,
                              void* d_out, int out_size)
{
    const float* query = (const float*)d_in[0];
    const float* key   = (const float*)d_in[1];
    const float* value = (const float*)d_in[2];
    const float* Wq    = (const float*)d_in[3];
    const float* bq    = (const float*)d_in[4];
    const float* Wk    = (const float*)d_in[5];
    const float* bk    = (const float*)d_in[6];
    const float* Wv    = (const float*)d_in[7];
    const float* bv    = (const float*)d_in[8];
    const float* Wo    = (const float*)d_in[9];
    const float* bo    = (const float*)d_in[10];

    void *pq, *pk, *pv, *patt;
    cudaGetSymbolAddress(&pq, g_q);
    cudaGetSymbolAddress(&pk, g_k);
    cudaGetSymbolAddress(&pv, g_v);
    cudaGetSymbolAddress(&patt, g_att);

    cudaFuncSetAttribute(attn_kernel, cudaFuncAttributeMaxDynamicSharedMemorySize,
                         ATTN_SMEM);

    dim3 pgrid(8, 32, 3);
    gemm_proj<<<pgrid, 256>>>(query, key, value, Wq, Wk, Wv, bq, bk, bv,
                              (float*)pq, (float*)pk, (float*)pv);

    dim3 agrid(S / BQ, B * H);  // (8, 32)
    attn_kernel<<<agrid, 128, ATTN_SMEM>>>((const float*)pq, (const float*)pk,
                                           (const float*)pv, (float*)patt);

    dim3 ggrid(8, 32);
    gemm_out<<<ggrid, 256>>>((const float*)patt, Wo, bo, (float*)d_out);
}

// round 9
// speedup vs baseline: 1.1778x; 1.1297x over previous
#include <cuda_runtime.h>
#include <cstdint>

// ===========================================================================
// MHA B=2,S=2048,E=1024,H=16,D=64 fp32.  SIMT f32x2 everywhere.
//  - GEMMs: R5 engine (128x128, BK=8, pk2-dup in regs) + launch_bounds(256,2)
//    -> 2 CTAs/SM (4 warps/SMSP).
//  - attention: R5 1-row/thread kernel (BQ=128) + launch_bounds(128,3)
//    -> 3 CTAs/SM (6 warps... 12 warps/SM), QSTR=68 aligned float4 Q reads.
//  2-row/thread attention measured twice as a loss (R7/R8) — abandoned.
// ===========================================================================

typedef unsigned long long ull;
#define DI __device__ __forceinline__

DI ull pk2(float lo, float hi) {
    ull r; asm("mov.b64 %0, {%1,%2};" : "=l"(r) : "f"(lo), "f"(hi)); return r;
}
DI void upk2(ull v, float& lo, float& hi) {
    asm("mov.b64 {%0,%1}, %2;" : "=f"(lo), "=f"(hi) : "l"(v));
}
DI ull ffma2(ull a, ull b, ull c) {
    ull d; asm("fma.rn.f32x2 %0, %1, %2, %3;" : "=l"(d) : "l"(a), "l"(b), "l"(c)); return d;
}
DI ull fmul2(ull a, ull b) {
    ull d; asm("mul.rn.f32x2 %0, %1, %2;" : "=l"(d) : "l"(a), "l"(b)); return d;
}

constexpr int B = 2, S = 2048, E = 1024, H = 16, D = 64;

__device__ float g_q[B * H * S * D];
__device__ float g_k[B * H * S * D];
__device__ float g_v[B * H * S * D];
__device__ float g_att[B * S * E];

// ---------------------------------------------------------------------------
// R5 GEMM engine, now with min-2-blocks launch bounds.
// ---------------------------------------------------------------------------
template <int MODE>
DI void gemm_body(const float* __restrict__ X, const float* __restrict__ W,
                  const float* __restrict__ bias, float* __restrict__ out)
{
    __shared__ __align__(16) float As[8][132];
    __shared__ __align__(16) float Ws[8][132];

    const int tid = threadIdx.x;
    const int tx = tid & 15, ty = tid >> 4;
    const int m0 = blockIdx.y * 128;
    const int n0 = blockIdx.x * 128;
    const int lr = tid >> 1;
    const int lc = (tid & 1) << 2;

    const float* Xp = X + (size_t)(m0 + lr) * 1024 + lc;
    const float* Wp = W + (size_t)(n0 + lr) * 1024 + lc;

    ull acc[8][4];
#pragma unroll
    for (int i = 0; i < 8; i++)
#pragma unroll
        for (int j = 0; j < 4; j++) acc[i][j] = 0ull;

    float4 av = *(const float4*)Xp;
    float4 wv = *(const float4*)Wp;

    for (int k0 = 0; k0 < 1024; k0 += 8) {
        __syncthreads();
        As[lc + 0][lr] = av.x; As[lc + 1][lr] = av.y;
        As[lc + 2][lr] = av.z; As[lc + 3][lr] = av.w;
        Ws[lc + 0][lr] = wv.x; Ws[lc + 1][lr] = wv.y;
        Ws[lc + 2][lr] = wv.z; Ws[lc + 3][lr] = wv.w;
        __syncthreads();
        if (k0 + 8 < 1024) {
            av = *(const float4*)(Xp + k0 + 8);
            wv = *(const float4*)(Wp + k0 + 8);
        }
#pragma unroll
        for (int kk = 0; kk < 8; kk++) {
            float4 a0 = *(const float4*)&As[kk][ty * 4];
            float4 a1 = *(const float4*)&As[kk][64 + ty * 4];
            ulonglong2 b0 = *(const ulonglong2*)&Ws[kk][tx * 4];
            ulonglong2 b1 = *(const ulonglong2*)&Ws[kk][64 + tx * 4];
            float a[8] = {a0.x, a0.y, a0.z, a0.w, a1.x, a1.y, a1.z, a1.w};
            ull bv[4] = {b0.x, b0.y, b1.x, b1.y};
#pragma unroll
            for (int i = 0; i < 8; i++) {
                ull a2 = pk2(a[i], a[i]);
#pragma unroll
                for (int j = 0; j < 4; j++) acc[i][j] = ffma2(a2, bv[j], acc[i][j]);
            }
        }
    }

    float4 bias0 = *(const float4*)&bias[n0 + tx * 4];
    float4 bias1 = *(const float4*)&bias[n0 + 64 + tx * 4];

#pragma unroll
    for (int i = 0; i < 8; i++) {
        int m = m0 + (i >> 2) * 64 + ty * 4 + (i & 3);
        float4 r0, r1;
        upk2(acc[i][0], r0.x, r0.y); upk2(acc[i][1], r0.z, r0.w);
        upk2(acc[i][2], r1.x, r1.y); upk2(acc[i][3], r1.z, r1.w);
        r0.x += bias0.x; r0.y += bias0.y; r0.z += bias0.z; r0.w += bias0.w;
        r1.x += bias1.x; r1.y += bias1.y; r1.z += bias1.z; r1.w += bias1.w;
        if (MODE == 0) {
            int bb = m >> 11, ss = m & 2047;
            int nA = n0 + tx * 4;
            int nB = n0 + 64 + tx * 4;
            int hA = nA >> 6, dA = nA & 63;
            int hB = nB >> 6, dB = nB & 63;
            *(float4*)&out[((size_t)(bb * H + hA) * S + ss) * D + dA] = r0;
            *(float4*)&out[((size_t)(bb * H + hB) * S + ss) * D + dB] = r1;
        } else {
            *(float4*)&out[(size_t)m * 1024 + n0 + tx * 4] = r0;
            *(float4*)&out[(size_t)m * 1024 + n0 + 64 + tx * 4] = r1;
        }
    }
}

__global__ __launch_bounds__(256, 2) void gemm_proj(const float* __restrict__ xq,
                                                    const float* __restrict__ xk,
                                                    const float* __restrict__ xv,
                                                    const float* __restrict__ Wq,
                                                    const float* __restrict__ Wk,
                                                    const float* __restrict__ Wv,
                                                    const float* __restrict__ bq,
                                                    const float* __restrict__ bk,
                                                    const float* __restrict__ bv,
                                                    float* __restrict__ oq,
                                                    float* __restrict__ ok,
                                                    float* __restrict__ ov)
{
    const int z = blockIdx.z;
    const float* X = (z == 0) ? xq : (z == 1) ? xk : xv;
    const float* W = (z == 0) ? Wq : (z == 1) ? Wk : Wv;
    const float* bb = (z == 0) ? bq : (z == 1) ? bk : bv;
    float* out = (z == 0) ? oq : (z == 1) ? ok : ov;
    gemm_body<0>(X, W, bb, out);
}

__global__ __launch_bounds__(256, 2) void gemm_out(const float* __restrict__ X,
                                                   const float* __restrict__ W,
                                                   const float* __restrict__ bias,
                                                   float* __restrict__ out)
{
    gemm_body<1>(X, W, bias, out);
}

// ---------------------------------------------------------------------------
// flash attention: BQ=128, 128 threads, 1 row/thread, 3 CTAs/SM.
// Q stride 68 (16B-aligned float4 rows); K transposed [d][68]; V [j][64].
// Group-wise online softmax, 16 keys/group.
// ---------------------------------------------------------------------------
constexpr int BQ = 128, TK = 64;
constexpr int QSTR = 68, KSTR = 68;
constexpr int ATTN_SMEM = (BQ * QSTR + D * KSTR + TK * D) * 4;  // 68608

__global__ __launch_bounds__(128, 3) void attn_kernel(const float* __restrict__ Q,
                                                      const float* __restrict__ K,
                                                      const float* __restrict__ V,
                                                      float* __restrict__ Oout)
{
    extern __shared__ float sm[];
    float* Qs  = sm;                  // [128][68]
    float* Kst = sm + BQ * QSTR;      // [64 d][68 keys]
    float* Vs  = Kst + D * KSTR;      // [64 keys][64 d]

    const int t  = threadIdx.x;
    const int bh = blockIdx.y;
    const int q0 = blockIdx.x * BQ;
    const float* Qb = Q + (size_t)bh * (S * D);
    const float* Kb = K + (size_t)bh * (S * D);
    const float* Vb = V + (size_t)bh * (S * D);

    const int dl = t & 63, rb = t >> 6;

#pragma unroll
    for (int i = 0; i < 64; i++) {
        int r = 2 * i + rb;
        Qs[r * QSTR + dl] = Qb[(size_t)(q0 + r) * D + dl] * 0.125f;
    }

    ull o2[32];
#pragma unroll
    for (int i = 0; i < 32; i++) o2[i] = 0ull;
    float m_run = -3.0e38f, l_run = 0.0f;

    const float* qrow = &Qs[t * QSTR];

    for (int kt = 0; kt < S; kt += TK) {
        __syncthreads();
#pragma unroll
        for (int i = 0; i < 32; i++) {
            int j = 2 * i + rb;
            Kst[dl * KSTR + j] = Kb[(size_t)(kt + j) * D + dl];
            Vs[j * D + dl]     = Vb[(size_t)(kt + j) * D + dl];
        }
        __syncthreads();

#pragma unroll
        for (int g = 0; g < 4; g++) {
            ull s2[8];
#pragma unroll
            for (int i = 0; i < 8; i++) s2[i] = 0ull;

#pragma unroll
            for (int dc = 0; dc < D; dc += 16) {
                float qf[16];
#pragma unroll
                for (int u = 0; u < 4; u++)
                    *(float4*)&qf[4 * u] = *(const float4*)&qrow[dc + 4 * u];
#pragma unroll
                for (int dd = 0; dd < 16; dd++) {
                    ull q2 = pk2(qf[dd], qf[dd]);
                    const ulonglong2* kr =
                        (const ulonglong2*)&Kst[(dc + dd) * KSTR + g * 16];
#pragma unroll
                    for (int u = 0; u < 4; u++) {
                        ulonglong2 kv = kr[u];
                        s2[2 * u]     = ffma2(q2, kv.x, s2[2 * u]);
                        s2[2 * u + 1] = ffma2(q2, kv.y, s2[2 * u + 1]);
                    }
                }
            }

            float gmax = -3.0e38f;
#pragma unroll
            for (int i = 0; i < 8; i++) {
                float x, y; upk2(s2[i], x, y);
                gmax = fmaxf(gmax, fmaxf(x, y));
            }
            if (__any_sync(0xffffffffu, gmax > m_run)) {
                float mnew = fmaxf(m_run, gmax);
                float alpha = __expf(m_run - mnew);
                l_run *= alpha;
                ull al2 = pk2(alpha, alpha);
#pragma unroll
                for (int i = 0; i < 32; i++) o2[i] = fmul2(o2[i], al2);
                m_run = mnew;
            }
            float lsum = 0.0f;
#pragma unroll
            for (int i = 0; i < 8; i++) {
                float x, y; upk2(s2[i], x, y);
                float p0 = __expf(x - m_run), p1 = __expf(y - m_run);
                lsum += p0 + p1;
                s2[i] = pk2(p0, p1);
            }
            l_run += lsum;

#pragma unroll
            for (int j2 = 0; j2 < 8; j2++) {
                int j = g * 16 + 2 * j2;
                float p0, p1; upk2(s2[j2], p0, p1);
                ull pa = pk2(p0, p0), pb = pk2(p1, p1);
                const ulonglong2* v0 = (const ulonglong2*)&Vs[j * D];
                const ulonglong2* v1 = (const ulonglong2*)&Vs[(j + 1) * D];
#pragma unroll
                for (int cp = 0; cp < 16; cp++) {
                    ulonglong2 va = v0[cp];
                    ulonglong2 vb = v1[cp];
                    o2[2 * cp]     = ffma2(pa, va.x, o2[2 * cp]);
                    o2[2 * cp + 1] = ffma2(pa, va.y, o2[2 * cp + 1]);
                    o2[2 * cp]     = ffma2(pb, vb.x, o2[2 * cp]);
                    o2[2 * cp + 1] = ffma2(pb, vb.y, o2[2 * cp + 1]);
                }
            }
        }
    }

    float inv_l = 1.0f / l_run;
    int bb = bh >> 4, hh = bh & 15;
    float* dst = Oout + (size_t)(bb * S + q0 + t) * E + hh * D;
#pragma unroll
    for (int cp = 0; cp < 16; cp++) {
        float x0, x1, x2, x3;
        upk2(o2[2 * cp], x0, x1);
        upk2(o2[2 * cp + 1], x2, x3);
        float4 o4 = { x0 * inv_l, x1 * inv_l, x2 * inv_l, x3 * inv_l };
        *(float4*)&dst[cp * 4] = o4;
    }
}

// ---------------------------------------------------------------------------
extern "C" void kernel_launch(void* const* d_in, const int* in_sizes, int n_in,
                              void* d_out, int out_size)
{
    const float* query = (const float*)d_in[0];
    const float* key   = (const float*)d_in[1];
    const float* value = (const float*)d_in[2];
    const float* Wq    = (const float*)d_in[3];
    const float* bq    = (const float*)d_in[4];
    const float* Wk    = (const float*)d_in[5];
    const float* bk    = (const float*)d_in[6];
    const float* Wv    = (const float*)d_in[7];
    const float* bv    = (const float*)d_in[8];
    const float* Wo    = (const float*)d_in[9];
    const float* bo    = (const float*)d_in[10];

    void *pq, *pk, *pv, *patt;
    cudaGetSymbolAddress(&pq, g_q);
    cudaGetSymbolAddress(&pk, g_k);
    cudaGetSymbolAddress(&pv, g_v);
    cudaGetSymbolAddress(&patt, g_att);

    cudaFuncSetAttribute(attn_kernel, cudaFuncAttributeMaxDynamicSharedMemorySize,
                         ATTN_SMEM);

    dim3 pgrid(8, 32, 3);
    gemm_proj<<<pgrid, 256>>>(query, key, value, Wq, Wk, Wv, bq, bk, bv,
                              (float*)pq, (float*)pk, (float*)pv);

    dim3 agrid(S / BQ, B * H);  // (16, 32)
    attn_kernel<<<agrid, 128, ATTN_SMEM>>>((const float*)pq, (const float*)pk,
                                           (const float*)pv, (float*)patt);

    dim3 ggrid(8, 32);
    gemm_out<<<ggrid, 256>>>((const float*)patt, Wo, bo, (float*)d_out);
}

// round 10
// speedup vs baseline: 1.3205x; 1.1211x over previous
#include <cuda_runtime.h>
#include <cstdint>

// ===========================================================================
// MHA B=2,S=2048,E=1024,H=16,D=64 fp32.  SIMT f32x2 everywhere.
//  - GEMMs: R5 engine + launch_bounds(256,2) (measured 562us proj).
//  - attention: KEY-SPLIT flash: 256 thr/CTA, thread owns (row = t&127,
//    key-half = t>>7). Per-thread state identical to R5 (no reg growth),
//    2x warps/SM. Final split-softmax merge via smem (aliases K/V buffers).
//    Q reads: stride-65 scalar (conflict-free). K/V reads: warp-broadcast.
// ===========================================================================

typedef unsigned long long ull;
#define DI __device__ __forceinline__

DI ull pk2(float lo, float hi) {
    ull r; asm("mov.b64 %0, {%1,%2};" : "=l"(r) : "f"(lo), "f"(hi)); return r;
}
DI void upk2(ull v, float& lo, float& hi) {
    asm("mov.b64 {%0,%1}, %2;" : "=f"(lo), "=f"(hi) : "l"(v));
}
DI ull ffma2(ull a, ull b, ull c) {
    ull d; asm("fma.rn.f32x2 %0, %1, %2, %3;" : "=l"(d) : "l"(a), "l"(b), "l"(c)); return d;
}
DI ull fmul2(ull a, ull b) {
    ull d; asm("mul.rn.f32x2 %0, %1, %2;" : "=l"(d) : "l"(a), "l"(b)); return d;
}

constexpr int B = 2, S = 2048, E = 1024, H = 16, D = 64;

__device__ float g_q[B * H * S * D];
__device__ float g_k[B * H * S * D];
__device__ float g_v[B * H * S * D];
__device__ float g_att[B * S * E];

// ---------------------------------------------------------------------------
// R5 GEMM engine with launch_bounds(256,2) (R9-measured best: 562us).
// ---------------------------------------------------------------------------
template <int MODE>
DI void gemm_body(const float* __restrict__ X, const float* __restrict__ W,
                  const float* __restrict__ bias, float* __restrict__ out)
{
    __shared__ __align__(16) float As[8][132];
    __shared__ __align__(16) float Ws[8][132];

    const int tid = threadIdx.x;
    const int tx = tid & 15, ty = tid >> 4;
    const int m0 = blockIdx.y * 128;
    const int n0 = blockIdx.x * 128;
    const int lr = tid >> 1;
    const int lc = (tid & 1) << 2;

    const float* Xp = X + (size_t)(m0 + lr) * 1024 + lc;
    const float* Wp = W + (size_t)(n0 + lr) * 1024 + lc;

    ull acc[8][4];
#pragma unroll
    for (int i = 0; i < 8; i++)
#pragma unroll
        for (int j = 0; j < 4; j++) acc[i][j] = 0ull;

    float4 av = *(const float4*)Xp;
    float4 wv = *(const float4*)Wp;

    for (int k0 = 0; k0 < 1024; k0 += 8) {
        __syncthreads();
        As[lc + 0][lr] = av.x; As[lc + 1][lr] = av.y;
        As[lc + 2][lr] = av.z; As[lc + 3][lr] = av.w;
        Ws[lc + 0][lr] = wv.x; Ws[lc + 1][lr] = wv.y;
        Ws[lc + 2][lr] = wv.z; Ws[lc + 3][lr] = wv.w;
        __syncthreads();
        if (k0 + 8 < 1024) {
            av = *(const float4*)(Xp + k0 + 8);
            wv = *(const float4*)(Wp + k0 + 8);
        }
#pragma unroll
        for (int kk = 0; kk < 8; kk++) {
            float4 a0 = *(const float4*)&As[kk][ty * 4];
            float4 a1 = *(const float4*)&As[kk][64 + ty * 4];
            ulonglong2 b0 = *(const ulonglong2*)&Ws[kk][tx * 4];
            ulonglong2 b1 = *(const ulonglong2*)&Ws[kk][64 + tx * 4];
            float a[8] = {a0.x, a0.y, a0.z, a0.w, a1.x, a1.y, a1.z, a1.w};
            ull bv[4] = {b0.x, b0.y, b1.x, b1.y};
#pragma unroll
            for (int i = 0; i < 8; i++) {
                ull a2 = pk2(a[i], a[i]);
#pragma unroll
                for (int j = 0; j < 4; j++) acc[i][j] = ffma2(a2, bv[j], acc[i][j]);
            }
        }
    }

    float4 bias0 = *(const float4*)&bias[n0 + tx * 4];
    float4 bias1 = *(const float4*)&bias[n0 + 64 + tx * 4];

#pragma unroll
    for (int i = 0; i < 8; i++) {
        int m = m0 + (i >> 2) * 64 + ty * 4 + (i & 3);
        float4 r0, r1;
        upk2(acc[i][0], r0.x, r0.y); upk2(acc[i][1], r0.z, r0.w);
        upk2(acc[i][2], r1.x, r1.y); upk2(acc[i][3], r1.z, r1.w);
        r0.x += bias0.x; r0.y += bias0.y; r0.z += bias0.z; r0.w += bias0.w;
        r1.x += bias1.x; r1.y += bias1.y; r1.z += bias1.z; r1.w += bias1.w;
        if (MODE == 0) {
            int bb = m >> 11, ss = m & 2047;
            int nA = n0 + tx * 4;
            int nB = n0 + 64 + tx * 4;
            int hA = nA >> 6, dA = nA & 63;
            int hB = nB >> 6, dB = nB & 63;
            *(float4*)&out[((size_t)(bb * H + hA) * S + ss) * D + dA] = r0;
            *(float4*)&out[((size_t)(bb * H + hB) * S + ss) * D + dB] = r1;
        } else {
            *(float4*)&out[(size_t)m * 1024 + n0 + tx * 4] = r0;
            *(float4*)&out[(size_t)m * 1024 + n0 + 64 + tx * 4] = r1;
        }
    }
}

__global__ __launch_bounds__(256, 2) void gemm_proj(const float* __restrict__ xq,
                                                    const float* __restrict__ xk,
                                                    const float* __restrict__ xv,
                                                    const float* __restrict__ Wq,
                                                    const float* __restrict__ Wk,
                                                    const float* __restrict__ Wv,
                                                    const float* __restrict__ bq,
                                                    const float* __restrict__ bk,
                                                    const float* __restrict__ bv,
                                                    float* __restrict__ oq,
                                                    float* __restrict__ ok,
                                                    float* __restrict__ ov)
{
    const int z = blockIdx.z;
    const float* X = (z == 0) ? xq : (z == 1) ? xk : xv;
    const float* W = (z == 0) ? Wq : (z == 1) ? Wk : Wv;
    const float* bb = (z == 0) ? bq : (z == 1) ? bk : bv;
    float* out = (z == 0) ? oq : (z == 1) ? ok : ov;
    gemm_body<0>(X, W, bb, out);
}

__global__ __launch_bounds__(256, 2) void gemm_out(const float* __restrict__ X,
                                                   const float* __restrict__ W,
                                                   const float* __restrict__ bias,
                                                   float* __restrict__ out)
{
    gemm_body<1>(X, W, bias, out);
}

// ---------------------------------------------------------------------------
// Key-split flash attention.
// BQ=128 rows/CTA, 256 threads: row = t&127, khalf = t>>7.
// Each thread runs the R5 per-row loop over HALF the keys of each tile
// (its 2 of the 4 16-key groups) with its own (m, l, o2[32]).
// End: split-softmax merge of the two halves via smem.
// Q in smem stride 65 (scalar reads, conflict-free); K transposed [d][68];
// V [j][64]. K/V inner reads are warp-broadcast (warps are khalf-uniform).
// ---------------------------------------------------------------------------
constexpr int BQ = 128, TK = 64;
constexpr int QSTR = 65, KSTR = 68;
// floats: Q 128*65=8320 | K 64*68=4352 | V 64*64=4096 | M/L 256  => 17024
constexpr int ATTN_SMEM = (BQ * QSTR + TK * KSTR + TK * D + 2 * 256) * 4;  // 68096

__global__ __launch_bounds__(256, 2) void attn_kernel(const float* __restrict__ Q,
                                                      const float* __restrict__ K,
                                                      const float* __restrict__ V,
                                                      float* __restrict__ Oout)
{
    extern __shared__ float sm[];
    float* Qs  = sm;                       // [128][65]
    float* Kst = sm + BQ * QSTR;           // [64 d][68 keys]
    float* Vs  = Kst + TK * KSTR;          // [64 keys][64 d]
    float* Ms  = Vs + TK * D;              // [256]
    float* Ls  = Ms + 256;                 // [256]

    const int t  = threadIdx.x;
    const int row = t & 127;
    const int khalf = t >> 7;
    const int bh = blockIdx.y;
    const int q0 = blockIdx.x * BQ;
    const float* Qb = Q + (size_t)bh * (S * D);
    const float* Kb = K + (size_t)bh * (S * D);
    const float* Vb = V + (size_t)bh * (S * D);

    // load Q tile (scaled): 128x64, 256 threads -> 32 elems each
#pragma unroll
    for (int i = 0; i < 32; i++) {
        int idx = i * 256 + t;
        int r = idx >> 6, d = idx & 63;
        Qs[r * QSTR + d] = Qb[(size_t)(q0 + r) * D + d] * 0.125f;
    }

    ull o2[32];
#pragma unroll
    for (int i = 0; i < 32; i++) o2[i] = 0ull;
    float m_run = -3.0e38f, l_run = 0.0f;

    const float* qrow = &Qs[row * QSTR];
    const int gbase = khalf * 2;

    for (int kt = 0; kt < S; kt += TK) {
        __syncthreads();
        // load K (transposed) + V: 64x64 each, 16 elems per thread
#pragma unroll
        for (int i = 0; i < 16; i++) {
            int idx = i * 256 + t;
            int j = idx >> 6, d = idx & 63;
            Kst[d * KSTR + j] = Kb[(size_t)(kt + j) * D + d];
            Vs[j * D + d]     = Vb[(size_t)(kt + j) * D + d];
        }
        __syncthreads();

#pragma unroll
        for (int gi = 0; gi < 2; gi++) {
            const int g = gbase + gi;
            ull s2[8];
#pragma unroll
            for (int i = 0; i < 8; i++) s2[i] = 0ull;

#pragma unroll
            for (int dc = 0; dc < D; dc += 16) {
                float qf[16];
#pragma unroll
                for (int u = 0; u < 16; u++) qf[u] = qrow[dc + u];
#pragma unroll
                for (int dd = 0; dd < 16; dd++) {
                    ull q2 = pk2(qf[dd], qf[dd]);
                    const ulonglong2* kr =
                        (const ulonglong2*)&Kst[(dc + dd) * KSTR + g * 16];
#pragma unroll
                    for (int u = 0; u < 4; u++) {
                        ulonglong2 kv = kr[u];
                        s2[2 * u]     = ffma2(q2, kv.x, s2[2 * u]);
                        s2[2 * u + 1] = ffma2(q2, kv.y, s2[2 * u + 1]);
                    }
                }
            }

            float gmax = -3.0e38f;
#pragma unroll
            for (int i = 0; i < 8; i++) {
                float x, y; upk2(s2[i], x, y);
                gmax = fmaxf(gmax, fmaxf(x, y));
            }
            if (__any_sync(0xffffffffu, gmax > m_run)) {
                float mnew = fmaxf(m_run, gmax);
                float alpha = __expf(m_run - mnew);
                l_run *= alpha;
                ull al2 = pk2(alpha, alpha);
#pragma unroll
                for (int i = 0; i < 32; i++) o2[i] = fmul2(o2[i], al2);
                m_run = mnew;
            }
            float lsum = 0.0f;
#pragma unroll
            for (int i = 0; i < 8; i++) {
                float x, y; upk2(s2[i], x, y);
                float p0 = __expf(x - m_run), p1 = __expf(y - m_run);
                lsum += p0 + p1;
                s2[i] = pk2(p0, p1);
            }
            l_run += lsum;

#pragma unroll
            for (int j2 = 0; j2 < 8; j2++) {
                int j = g * 16 + 2 * j2;
                float p0, p1; upk2(s2[j2], p0, p1);
                ull pa = pk2(p0, p0), pb = pk2(p1, p1);
                const ulonglong2* v0 = (const ulonglong2*)&Vs[j * D];
                const ulonglong2* v1 = (const ulonglong2*)&Vs[(j + 1) * D];
#pragma unroll
                for (int cp = 0; cp < 16; cp++) {
                    ulonglong2 va = v0[cp];
                    ulonglong2 vb = v1[cp];
                    o2[2 * cp]     = ffma2(pa, va.x, o2[2 * cp]);
                    o2[2 * cp + 1] = ffma2(pa, va.y, o2[2 * cp + 1]);
                    o2[2 * cp]     = ffma2(pb, vb.x, o2[2 * cp]);
                    o2[2 * cp + 1] = ffma2(pb, vb.y, o2[2 * cp + 1]);
                }
            }
        }
    }

    // ---- split-softmax merge of the two key-halves ----
    Ms[t] = m_run;
    Ls[t] = l_run;
    __syncthreads();

    // upper half dumps its o2 into smem (aliases Kst..Vs; stride 33 ull ->
    // conflict-free; region = 8448 floats = 128 rows * 33 ull exactly)
    ull* Os = (ull*)Kst;
    if (khalf == 1) {
        ull* dsts = Os + (size_t)row * 33;
#pragma unroll
        for (int i = 0; i < 32; i++) dsts[i] = o2[i];
    }
    __syncthreads();

    if (khalf == 0) {
        float m1 = Ms[row + 128], l1 = Ls[row + 128];
        float M = fmaxf(m_run, m1);
        float a0 = __expf(m_run - M), a1 = __expf(m1 - M);
        float l = l_run * a0 + l1 * a1;
        float s0 = a0 / l, s1 = a1 / l;
        const ull* srcs = Os + (size_t)row * 33;
        int bb = bh >> 4, hh = bh & 15;
        float* dst = Oout + (size_t)(bb * S + q0 + row) * E + hh * D;
#pragma unroll
        for (int cp = 0; cp < 16; cp++) {
            float x0, x1, x2, x3, y0, y1, y2, y3;
            upk2(o2[2 * cp], x0, x1);
            upk2(o2[2 * cp + 1], x2, x3);
            ull u0 = srcs[2 * cp], u1 = srcs[2 * cp + 1];
            upk2(u0, y0, y1);
            upk2(u1, y2, y3);
            float4 o4 = { x0 * s0 + y0 * s1, x1 * s0 + y1 * s1,
                          x2 * s0 + y2 * s1, x3 * s0 + y3 * s1 };
            *(float4*)&dst[cp * 4] = o4;
        }
    }
}

// ---------------------------------------------------------------------------
extern "C" void kernel_launch(void* const* d_in, const int* in_sizes, int n_in,
                              void* d_out, int out_size)
{
    const float* query = (const float*)d_in[0];
    const float* key   = (const float*)d_in[1];
    const float* value = (const float*)d_in[2];
    const float* Wq    = (const float*)d_in[3];
    const float* bq    = (const float*)d_in[4];
    const float* Wk    = (const float*)d_in[5];
    const float* bk    = (const float*)d_in[6];
    const float* Wv    = (const float*)d_in[7];
    const float* bv    = (const float*)d_in[8];
    const float* Wo    = (const float*)d_in[9];
    const float* bo    = (const float*)d_in[10];

    void *pq, *pk, *pv, *patt;
    cudaGetSymbolAddress(&pq, g_q);
    cudaGetSymbolAddress(&pk, g_k);
    cudaGetSymbolAddress(&pv, g_v);
    cudaGetSymbolAddress(&patt, g_att);

    cudaFuncSetAttribute(attn_kernel, cudaFuncAttributeMaxDynamicSharedMemorySize,
                         ATTN_SMEM);

    dim3 pgrid(8, 32, 3);
    gemm_proj<<<pgrid, 256>>>(query, key, value, Wq, Wk, Wv, bq, bk, bv,
                              (float*)pq, (float*)pk, (float*)pv);

    dim3 agrid(S / BQ, B * H);  // (16, 32)
    attn_kernel<<<agrid, 256, ATTN_SMEM>>>((const float*)pq, (const float*)pk,
                                           (const float*)pv, (float*)patt);

    dim3 ggrid(8, 32);
    gemm_out<<<ggrid, 256>>>((const float*)patt, Wo, bo, (float*)d_out);
}